// round 13
// baseline (speedup 1.0000x reference)
#include <cuda_runtime.h>
#include <cuda_bf16.h>
#include <math.h>
#include <stdint.h>

#define HDIM 1024
#define BDIM 128
#define TDIM 128
#define G3   (3 * HDIM)
#define BH   (BDIM * HDIM)

// Wf: per-GRU packed W_hh B-fragments: [which][bx][c][gate][lane] uint4 {BHi0,BHi1,BLo0,BLo1}
#define WF_PER (128 * 64 * 3 * 32)
// Hfw: h in A-fragment layout, u32 words:
// [par(2)][hi:65536 u32 | lo:65536 u32], frag idx = ((c*8+mt)*32+lane)*4+reg
#define HFW_U32 (2 * 131072)

// ----------------------------- scratch (device globals) ----------------------
__device__ float g_gates_p[(size_t)BDIM * TDIM * G3];
__device__ float g_gates_h[(size_t)BDIM * TDIM * G3];
__device__ float g_op[(size_t)TDIM * BDIM * HDIM];      // premise h, [T,B,H]
__device__ float g_hbuf[BH];                            // final hypothesis h
__device__ uint4 g_Wf[2 * WF_PER];
__device__ uint32_t g_Hfw[HFW_U32];
__device__ float g_WyT[HDIM * HDIM];
__device__ float g_WyM[(size_t)TDIM * BDIM * HDIM];
__device__ float g_Wh[BH];
__device__ float g_r[BH];
__device__ float g_G1[BH];
__device__ float g_G2[BH];
__device__ float g_hstar[BH];

__device__ unsigned g_arrive  = 0;
__device__ unsigned g_release = 0;

__device__ __forceinline__ float sigmoidf_(float x) { return 1.0f / (1.0f + expf(-x)); }

__device__ __forceinline__ uint32_t f2tf32(float x) {
    uint32_t r;
    asm("cvt.rna.tf32.f32 %0, %1;" : "=r"(r) : "f"(x));
    return r;
}

__device__ __forceinline__ void mma_tf32(float* d, const uint32_t* a, const uint32_t* b) {
    asm("mma.sync.aligned.m16n8k8.row.col.f32.tf32.tf32.f32 "
        "{%0,%1,%2,%3},{%4,%5,%6,%7},{%8,%9},{%0,%1,%2,%3};"
        : "+f"(d[0]), "+f"(d[1]), "+f"(d[2]), "+f"(d[3])
        : "r"(a[0]), "r"(a[1]), "r"(a[2]), "r"(a[3]), "r"(b[0]), "r"(b[1]));
}

__device__ __forceinline__ void mma_bf16(float* d, const uint32_t* a, uint32_t b0, uint32_t b1) {
    asm("mma.sync.aligned.m16n8k16.row.col.f32.bf16.bf16.f32 "
        "{%0,%1,%2,%3},{%4,%5,%6,%7},{%8,%9},{%0,%1,%2,%3};"
        : "+f"(d[0]), "+f"(d[1]), "+f"(d[2]), "+f"(d[3])
        : "r"(a[0]), "r"(a[1]), "r"(a[2]), "r"(a[3]), "r"(b0), "r"(b1));
}

__device__ __forceinline__ uint32_t pack_hi(float a, float b) {
    __nv_bfloat16 x = __float2bfloat16(a), y = __float2bfloat16(b);
    return (uint32_t)*(uint16_t*)&x | ((uint32_t)*(uint16_t*)&y << 16);
}

// ----------------------------- pack W_hh into B-fragment layout --------------
__global__ void pack_w(const float* __restrict__ Wp, const float* __restrict__ Whh_h,
                       uint4* __restrict__ Wf)
{
    int idx = blockIdx.x * blockDim.x + threadIdx.x;   // [which][bx][c][gate][lane]
    if (idx >= 2 * WF_PER) return;
    int lane = idx & 31;
    int gate = (idx >> 5) % 3;
    int c    = (idx / 96) & 63;
    int bx   = (idx / 6144) & 127;
    int which = idx / WF_PER;
    int g = lane >> 2, tg = lane & 3;
    const float* W = which ? Whh_h : Wp;
    const float* row = W + (size_t)(gate * HDIM + bx * 8 + g) * HDIM + c * 16;

    float v0 = row[2 * tg],     v1 = row[2 * tg + 1];
    float v2 = row[2 * tg + 8], v3 = row[2 * tg + 9];
    __nv_bfloat16 h0 = __float2bfloat16(v0), h1 = __float2bfloat16(v1);
    __nv_bfloat16 h2 = __float2bfloat16(v2), h3 = __float2bfloat16(v3);
    uint4 o;
    o.x = (uint32_t)*(uint16_t*)&h0 | ((uint32_t)*(uint16_t*)&h1 << 16);
    o.y = (uint32_t)*(uint16_t*)&h2 | ((uint32_t)*(uint16_t*)&h3 << 16);
    o.z = pack_hi(v0 - __bfloat162float(h0), v1 - __bfloat162float(h1));
    o.w = pack_hi(v2 - __bfloat162float(h2), v3 - __bfloat162float(h3));
    Wf[idx] = o;
}

__global__ void transpose1024(const float* __restrict__ in, float* __restrict__ out)
{
    __shared__ float t[32][33];
    int x = blockIdx.x * 32 + threadIdx.x;
    int y0 = blockIdx.y * 32;
    for (int r = threadIdx.y; r < 32; r += 8)
        t[r][threadIdx.x] = in[(size_t)(y0 + r) * HDIM + x];
    __syncthreads();
    int xo = blockIdx.y * 32 + threadIdx.x;
    for (int r = threadIdx.y; r < 32; r += 8)
        out[(size_t)(blockIdx.x * 32 + r) * HDIM + xo] = t[threadIdx.x][r];
}

// ----------------------------- tf32 mma GEMM ---------------------------------
template <bool BIAS>
__global__ void __launch_bounds__(256) gemm_tf32(
    const float* __restrict__ A, const float* __restrict__ Bw,
    const float* __restrict__ bias, float* __restrict__ C,
    int M, int N, int K)
{
    __shared__ uint32_t As[32][132];
    __shared__ uint32_t Bs[32][132];

    const int tid = threadIdx.x;
    const int lane = tid & 31, wid = tid >> 5;
    const int g = lane >> 2, tg = lane & 3;
    const int wm = (wid & 3) * 32;
    const int wn = (wid >> 2) * 64;
    const int m0 = blockIdx.y * 128, n0 = blockIdx.x * 128;

    float acc[2][8][4];
#pragma unroll
    for (int a = 0; a < 2; a++)
#pragma unroll
        for (int b = 0; b < 8; b++)
#pragma unroll
            for (int c = 0; c < 4; c++) acc[a][b][c] = 0.f;

    for (int k0 = 0; k0 < K; k0 += 32) {
#pragma unroll
        for (int r = 0; r < 4; r++) {
            int idx = tid + r * 256;
            int row = idx >> 3, kq = (idx & 7) * 4;
            float4 av = *(const float4*)&A[(size_t)(m0 + row) * K + k0 + kq];
            As[kq + 0][row] = f2tf32(av.x);
            As[kq + 1][row] = f2tf32(av.y);
            As[kq + 2][row] = f2tf32(av.z);
            As[kq + 3][row] = f2tf32(av.w);
            float4 bv = *(const float4*)&Bw[(size_t)(n0 + row) * K + k0 + kq];
            Bs[kq + 0][row] = f2tf32(bv.x);
            Bs[kq + 1][row] = f2tf32(bv.y);
            Bs[kq + 2][row] = f2tf32(bv.z);
            Bs[kq + 3][row] = f2tf32(bv.w);
        }
        __syncthreads();
#pragma unroll
        for (int kk = 0; kk < 32; kk += 8) {
            uint32_t af[2][4], bf[8][2];
#pragma unroll
            for (int mt = 0; mt < 2; mt++) {
                af[mt][0] = As[kk + tg][wm + mt * 16 + g];
                af[mt][1] = As[kk + tg][wm + mt * 16 + g + 8];
                af[mt][2] = As[kk + tg + 4][wm + mt * 16 + g];
                af[mt][3] = As[kk + tg + 4][wm + mt * 16 + g + 8];
            }
#pragma unroll
            for (int nt = 0; nt < 8; nt++) {
                bf[nt][0] = Bs[kk + tg][wn + nt * 8 + g];
                bf[nt][1] = Bs[kk + tg + 4][wn + nt * 8 + g];
            }
#pragma unroll
            for (int mt = 0; mt < 2; mt++)
#pragma unroll
                for (int nt = 0; nt < 8; nt++)
                    mma_tf32(acc[mt][nt], af[mt], bf[nt]);
        }
        __syncthreads();
    }

#pragma unroll
    for (int mt = 0; mt < 2; mt++) {
#pragma unroll
        for (int nt = 0; nt < 8; nt++) {
            int row = m0 + wm + mt * 16 + g;
            int col = n0 + wn + nt * 8 + 2 * tg;
            float b0 = BIAS ? bias[col] : 0.f;
            float b1 = BIAS ? bias[col + 1] : 0.f;
            C[(size_t)row * N + col]       = acc[mt][nt][0] + b0;
            C[(size_t)row * N + col + 1]   = acc[mt][nt][1] + b1;
            C[(size_t)(row + 8) * N + col]     = acc[mt][nt][2] + b0;
            C[(size_t)(row + 8) * N + col + 1] = acc[mt][nt][3] + b1;
        }
    }
}

// ----------------------------- persistent GRU scan ---------------------------
// 128 blocks x 256 thr (8 warps). Warps split 2(M-halves of 64 batch) x 4(K
// quarters of 256 k). W B-fragments resident in smem (96 KB, read w/o
// duplication per K-quarter x2). A fragments via direct LDG.128 from L2,
// depth-2 pipeline. Partial D reduced through a 57 KB smem buffer.
// dyn smem: Wsm uint4[6144] | P float[8*1792]
#define PSTRIDE 28
#define PWARP   (64 * PSTRIDE)                 // 1792 floats per warp
#define SMEM_BYTES (6144 * 16 + 8 * PWARP * 4) // 98304 + 57344 = 155648

__global__ void __launch_bounds__(256) gru_scan_persistent(
    const float* __restrict__ gates_p, const float* __restrict__ gates_h,
    const uint4* __restrict__ Wf,
    const float* __restrict__ pbhh, const float* __restrict__ hbhh,
    float* __restrict__ op, float* __restrict__ hbuf, uint32_t* __restrict__ HfW)
{
    extern __shared__ uint4 sm4[];
    uint4* Wsm = sm4;                         // 6144 uint4
    float* Psm = (float*)(sm4 + 6144);        // 8 * 1792 floats

    const int tid = threadIdx.x, lane = tid & 31, wid = tid >> 5;
    const int kp = wid & 3, mh = wid >> 2;    // K-quarter, M-half
    const int bx = blockIdx.x;
    const int hc = bx * 8;
    const int b  = tid & 127;                 // epilogue batch row
    const int ch = tid >> 7;                  // epilogue col-half (4 cols)

    const unsigned rel0 = *(volatile unsigned*)&g_release;

    // premise W -> smem
    {
        const uint4* src = Wf + (size_t)bx * 6144;
        for (int i = tid; i < 6144; i += 256) Wsm[i] = src[i];
    }
    __syncthreads();

    // epilogue constants
    float hp[4] = {0.f, 0.f, 0.f, 0.f};
    float bsr[4], bsz[4], bsn[4];
    {
        int c0 = hc + ch * 4;
#pragma unroll
        for (int j = 0; j < 4; j++) {
            bsr[j] = pbhh[c0 + j];
            bsz[j] = pbhh[HDIM + c0 + j];
            bsn[j] = pbhh[2 * HDIM + c0 + j];
        }
    }

    // producer fragment-store indices
    const int c_p  = bx >> 1;
    const int mt_p = b >> 4;
    const int koff = (bx & 1) * 8 + ch * 4;
    const int reg_p = ((b >> 3) & 1) + ((koff & 8) ? 2 : 0);
    const int lane0 = (b & 7) * 4 + ((koff & 7) >> 1);
    const uint32_t hibase = (uint32_t)(((c_p * 8 + mt_p) * 32 + lane0) * 4 + reg_p);

    for (int s = 0; s < 256; s++) {
        const bool prem = s < 128;
        const int t = s & 127;

        if (s == 128) {
            const uint4* src = Wf + (size_t)WF_PER + (size_t)bx * 6144;
            for (int i = tid; i < 6144; i += 256) Wsm[i] = src[i];
            __syncthreads();
            int c0 = hc + ch * 4;
#pragma unroll
            for (int j = 0; j < 4; j++) {
                bsr[j] = hbhh[c0 + j];
                bsz[j] = hbhh[HDIM + c0 + j];
                bsn[j] = hbhh[2 * HDIM + c0 + j];
            }
        }

        // gx prefetch (independent of h)
        const float* gx = prem ? gates_p : gates_h;
        const float* gxp = gx + ((size_t)b * TDIM + t) * G3 + hc + ch * 4;
        float4 gR = __ldg((const float4*)(gxp));
        float4 gZ = __ldg((const float4*)(gxp + HDIM));
        float4 gN = __ldg((const float4*)(gxp + 2 * HDIM));
        float gr[4] = {gR.x, gR.y, gR.z, gR.w};
        float gz[4] = {gZ.x, gZ.y, gZ.z, gZ.w};
        float gn[4] = {gN.x, gN.y, gN.z, gN.w};

        if (s > 0) {
            const int par = (s - 1) & 1;
            const uint4* ahi = (const uint4*)(HfW + (size_t)par * 131072);
            const uint4* alo = ahi + 16384;
            const int c0 = kp * 16;

            float acc[4][3][4];
#pragma unroll
            for (int m = 0; m < 4; m++)
#pragma unroll
                for (int gt = 0; gt < 3; gt++)
#pragma unroll
                    for (int r = 0; r < 4; r++) acc[m][gt][r] = 0.f;

            uint4 bufh[2][4], bufl[2][4];
#pragma unroll
            for (int m = 0; m < 4; m++) {
                int f = (c0 * 8 + mh * 4 + m) * 32 + lane;
                bufh[0][m] = __ldg(&ahi[f]);
                bufl[0][m] = __ldg(&alo[f]);
            }
#pragma unroll
            for (int i = 0; i < 16; i++) {
                const int cur = i & 1, nxt = cur ^ 1;
                const int c = c0 + i;
                if (i < 15) {
#pragma unroll
                    for (int m = 0; m < 4; m++) {
                        int f = ((c + 1) * 8 + mh * 4 + m) * 32 + lane;
                        bufh[nxt][m] = __ldg(&ahi[f]);
                        bufl[nxt][m] = __ldg(&alo[f]);
                    }
                }
#pragma unroll
                for (int gt = 0; gt < 3; gt++) {
                    uint4 w4 = Wsm[(c * 3 + gt) * 32 + lane];
#pragma unroll
                    for (int m = 0; m < 4; m++) {
                        mma_bf16(acc[m][gt], (const uint32_t*)&bufh[cur][m], w4.x, w4.y);
                        mma_bf16(acc[m][gt], (const uint32_t*)&bufh[cur][m], w4.z, w4.w);
                        mma_bf16(acc[m][gt], (const uint32_t*)&bufl[cur][m], w4.x, w4.y);
                    }
                }
            }

            // store partials
            float* Pw = Psm + wid * PWARP;
#pragma unroll
            for (int m = 0; m < 4; m++)
#pragma unroll
                for (int gt = 0; gt < 3; gt++)
#pragma unroll
                    for (int r = 0; r < 4; r++) {
                        int rowl = m * 16 + (lane >> 2) + 8 * (r >> 1);
                        int col  = gt * 8 + (lane & 3) * 2 + (r & 1);
                        Pw[rowl * PSTRIDE + col] = acc[m][gt][r];
                    }
        }
        __syncthreads();

        // epilogue: thread (b, 4 cols at hc+ch*4)
        float d0[4] = {0, 0, 0, 0}, d1[4] = {0, 0, 0, 0}, d2[4] = {0, 0, 0, 0};
        if (s > 0) {
            const float4* P4 = (const float4*)Psm;
            const int mhb = b >> 6, rowl = b & 63;
            const int base = rowl * PSTRIDE + ch * 4;
#pragma unroll
            for (int kq = 0; kq < 4; kq++) {
                int wb = (mhb * 4 + kq) * PWARP;
                float4 v0 = P4[(wb + base) >> 2];
                float4 v1 = P4[(wb + base + 8) >> 2];
                float4 v2 = P4[(wb + base + 16) >> 2];
                d0[0] += v0.x; d0[1] += v0.y; d0[2] += v0.z; d0[3] += v0.w;
                d1[0] += v1.x; d1[1] += v1.y; d1[2] += v1.z; d1[3] += v1.w;
                d2[0] += v2.x; d2[1] += v2.y; d2[2] += v2.z; d2[3] += v2.w;
            }
        }

        float h[4];
#pragma unroll
        for (int j = 0; j < 4; j++) {
            float r = sigmoidf_(gr[j] + d0[j] + bsr[j]);
            float z = sigmoidf_(gz[j] + d1[j] + bsz[j]);
            float n = tanhf(gn[j] + r * (d2[j] + bsn[j]));
            h[j] = (1.f - z) * n + z * hp[j];
            hp[j] = h[j];
        }

        // fp32 stores
        if (prem) {
            float4* dst = (float4*)(op + (size_t)t * BH + (size_t)b * HDIM + hc + ch * 4);
            *dst = make_float4(h[0], h[1], h[2], h[3]);
        } else if (s == 255) {
            float4* dst = (float4*)(hbuf + (size_t)b * HDIM + hc + ch * 4);
            *dst = make_float4(h[0], h[1], h[2], h[3]);
        }

        // A-fragment hi/lo stores
        {
            __nv_bfloat16 q0 = __float2bfloat16(h[0]), q1 = __float2bfloat16(h[1]);
            __nv_bfloat16 q2 = __float2bfloat16(h[2]), q3 = __float2bfloat16(h[3]);
            uint32_t hiw0 = (uint32_t)*(uint16_t*)&q0 | ((uint32_t)*(uint16_t*)&q1 << 16);
            uint32_t hiw1 = (uint32_t)*(uint16_t*)&q2 | ((uint32_t)*(uint16_t*)&q3 << 16);
            uint32_t low0 = pack_hi(h[0] - __bfloat162float(q0), h[1] - __bfloat162float(q1));
            uint32_t low1 = pack_hi(h[2] - __bfloat162float(q2), h[3] - __bfloat162float(q3));
            uint32_t* base = HfW + (size_t)(s & 1) * 131072 + hibase;
            base[0]         = hiw0;
            base[4]         = hiw1;
            base[65536]     = low0;
            base[65536 + 4] = low1;
        }

        // grid barrier (tight spin)
        __threadfence();
        __syncthreads();
        if (tid == 0) {
            unsigned r = atomicAdd(&g_arrive, 1u);
            if ((r & 127u) == 127u) atomicAdd(&g_release, 1u);
            while ((unsigned)(*(volatile unsigned*)&g_release - rel0) < (unsigned)(s + 1)) { }
            __threadfence();
        }
        __syncthreads();
    }
}

// ----------------------------- fp32 GEMM for small matmuls -------------------
template <bool TRANSB, bool BIAS>
__global__ void gemm_tiled(const float* __restrict__ A, const float* __restrict__ Bm,
                           const float* __restrict__ bias, float* __restrict__ C,
                           int M, int N, int K)
{
    __shared__ float As[8][132];
    __shared__ float Bs[8][132];

    const int tid = threadIdx.x;
    const int tx = tid & 15, ty = tid >> 4;
    const int m0 = blockIdx.y * 128, n0 = blockIdx.x * 128;

    float acc[8][8];
#pragma unroll
    for (int i = 0; i < 8; i++)
#pragma unroll
        for (int j = 0; j < 8; j++) acc[i][j] = 0.f;

    const int a_row = tid >> 1;
    const int a_k4  = (tid & 1) * 4;
    const int b_kr  = tid >> 5;
    const int b_n4  = (tid & 31) * 4;

    for (int k0 = 0; k0 < K; k0 += 8) {
        float4 av = *(const float4*)&A[(size_t)(m0 + a_row) * K + k0 + a_k4];
        As[a_k4 + 0][a_row] = av.x;
        As[a_k4 + 1][a_row] = av.y;
        As[a_k4 + 2][a_row] = av.z;
        As[a_k4 + 3][a_row] = av.w;
        if (TRANSB) {
            float4 bv = *(const float4*)&Bm[(size_t)(n0 + a_row) * K + k0 + a_k4];
            Bs[a_k4 + 0][a_row] = bv.x;
            Bs[a_k4 + 1][a_row] = bv.y;
            Bs[a_k4 + 2][a_row] = bv.z;
            Bs[a_k4 + 3][a_row] = bv.w;
        } else {
            float4 bv = *(const float4*)&Bm[(size_t)(k0 + b_kr) * N + n0 + b_n4];
            Bs[b_kr][b_n4 + 0] = bv.x;
            Bs[b_kr][b_n4 + 1] = bv.y;
            Bs[b_kr][b_n4 + 2] = bv.z;
            Bs[b_kr][b_n4 + 3] = bv.w;
        }
        __syncthreads();
#pragma unroll
        for (int kk = 0; kk < 8; kk++) {
            float a[8], b[8];
#pragma unroll
            for (int i = 0; i < 8; i++) a[i] = As[kk][ty + 16 * i];
#pragma unroll
            for (int j = 0; j < 8; j++) b[j] = Bs[kk][tx + 16 * j];
#pragma unroll
            for (int i = 0; i < 8; i++)
#pragma unroll
                for (int j = 0; j < 8; j++) acc[i][j] += a[i] * b[j];
        }
        __syncthreads();
    }

#pragma unroll
    for (int i = 0; i < 8; i++) {
        int m = m0 + ty + 16 * i;
#pragma unroll
        for (int j = 0; j < 8; j++) {
            int n = n0 + tx + 16 * j;
            float v = acc[i][j];
            if (BIAS) v += bias[n];
            C[(size_t)m * N + n] = v;
        }
    }
}

// ----------------------------- attention -------------------------------------
__global__ void attn_kernel(const float* __restrict__ WyM, const float* __restrict__ Wh,
                            const float* __restrict__ Walpha, const float* __restrict__ op,
                            float* __restrict__ rout)
{
    __shared__ float sc[128];
    __shared__ float red[256];
    const int b = blockIdx.x;
    const int tid = threadIdx.x;
    const int lane = tid & 31;
    const int warp = tid >> 5;

    for (int t = warp; t < TDIM; t += 8) {
        const float* wy = WyM + ((size_t)t * BDIM + b) * HDIM;
        const float* wh = Wh + (size_t)b * HDIM;
        float s = 0.f;
        for (int d = lane; d < HDIM; d += 32)
            s += tanhf(wy[d] + wh[d]) * Walpha[d];
#pragma unroll
        for (int o = 16; o > 0; o >>= 1) s += __shfl_xor_sync(0xffffffffu, s, o);
        if (lane == 0) sc[t] = s;
    }
    __syncthreads();

    float v = (tid < 128) ? sc[tid] : -INFINITY;
    red[tid] = v;
    __syncthreads();
    for (int s = 128; s > 0; s >>= 1) {
        if (tid < s) red[tid] = fmaxf(red[tid], red[tid + s]);
        __syncthreads();
    }
    float mx = red[0];
    __syncthreads();
    float e = (tid < 128) ? expf(sc[tid] - mx) : 0.f;
    red[tid] = e;
    __syncthreads();
    for (int s = 128; s > 0; s >>= 1) {
        if (tid < s) red[tid] += red[tid + s];
        __syncthreads();
    }
    float sum = red[0];
    __syncthreads();
    if (tid < 128) sc[tid] = e / sum;
    __syncthreads();

    for (int h = tid; h < HDIM; h += 256) {
        float acc = 0.f;
        for (int t = 0; t < TDIM; t++)
            acc += sc[t] * op[((size_t)t * BDIM + b) * HDIM + h];
        rout[(size_t)b * HDIM + h] = acc;
    }
}

__global__ void combine_tanh(const float* __restrict__ a, const float* __restrict__ b,
                             float* __restrict__ c, int n)
{
    int i = blockIdx.x * blockDim.x + threadIdx.x;
    if (i < n) c[i] = tanhf(a[i] + b[i]);
}

__global__ void final_kernel(const float* __restrict__ hstar, const float* __restrict__ outw,
                             const float* __restrict__ outb, float* __restrict__ out)
{
    __shared__ float red[128];
    __shared__ float lg[3];
    const int b = blockIdx.x;
    const int tid = threadIdx.x;

    for (int c = 0; c < 3; c++) {
        float p = 0.f;
        for (int h = tid; h < HDIM; h += 128)
            p += hstar[(size_t)b * HDIM + h] * outw[(size_t)c * HDIM + h];
        red[tid] = p;
        __syncthreads();
        for (int s = 64; s > 0; s >>= 1) {
            if (tid < s) red[tid] += red[tid + s];
            __syncthreads();
        }
        if (tid == 0) lg[c] = tanhf(red[0] + outb[c]);
        __syncthreads();
    }
    if (tid == 0) {
        float m = fmaxf(lg[0], fmaxf(lg[1], lg[2]));
        float s = expf(lg[0] - m) + expf(lg[1] - m) + expf(lg[2] - m);
        float lse = logf(s);
        for (int c = 0; c < 3; c++) out[b * 3 + c] = lg[c] - m - lse;
    }
}

// ----------------------------- launch ----------------------------------------
extern "C" void kernel_launch(void* const* d_in, const int* in_sizes, int n_in,
                              void* d_out, int out_size)
{
    const float* premise    = (const float*)d_in[0];
    const float* hypothesis = (const float*)d_in[1];
    const float* p_Wih = (const float*)d_in[2];
    const float* p_Whh = (const float*)d_in[3];
    const float* p_bih = (const float*)d_in[4];
    const float* p_bhh = (const float*)d_in[5];
    const float* h_Wih = (const float*)d_in[6];
    const float* h_Whh = (const float*)d_in[7];
    const float* h_bih = (const float*)d_in[8];
    const float* h_bhh = (const float*)d_in[9];
    const float* W_y     = (const float*)d_in[10];
    const float* W_h     = (const float*)d_in[11];
    const float* W_alpha = (const float*)d_in[12];
    const float* W_x     = (const float*)d_in[13];
    const float* W_p     = (const float*)d_in[14];
    const float* out_w   = (const float*)d_in[15];
    const float* out_b   = (const float*)d_in[16];

    float *gates_p, *gates_h, *op, *hbuf, *WyT, *WyM, *Whs, *rs, *G1, *G2, *hstar;
    uint4* Wf;
    uint32_t* HfW;
    cudaGetSymbolAddress((void**)&gates_p, g_gates_p);
    cudaGetSymbolAddress((void**)&gates_h, g_gates_h);
    cudaGetSymbolAddress((void**)&op,      g_op);
    cudaGetSymbolAddress((void**)&hbuf,    g_hbuf);
    cudaGetSymbolAddress((void**)&Wf,      g_Wf);
    cudaGetSymbolAddress((void**)&HfW,     g_Hfw);
    cudaGetSymbolAddress((void**)&WyT,     g_WyT);
    cudaGetSymbolAddress((void**)&WyM,     g_WyM);
    cudaGetSymbolAddress((void**)&Whs,     g_Wh);
    cudaGetSymbolAddress((void**)&rs,      g_r);
    cudaGetSymbolAddress((void**)&G1,      g_G1);
    cudaGetSymbolAddress((void**)&G2,      g_G2);
    cudaGetSymbolAddress((void**)&hstar,   g_hstar);

    const int MB = TDIM * BDIM;

    // prep
    pack_w<<<(2 * WF_PER + 255) / 256, 256>>>(p_Whh, h_Whh, Wf);
    transpose1024<<<dim3(32, 32), dim3(32, 8)>>>(W_y, WyT);

    // input-gate GEMMs
    gemm_tf32<true><<<dim3(G3 / 128, MB / 128), 256>>>(
        premise, p_Wih, p_bih, gates_p, MB, G3, HDIM);
    gemm_tf32<true><<<dim3(G3 / 128, MB / 128), 256>>>(
        hypothesis, h_Wih, h_bih, gates_h, MB, G3, HDIM);

    // persistent scan
    static bool attr_set = false;
    if (!attr_set) {
        cudaFuncSetAttribute(gru_scan_persistent,
                             cudaFuncAttributeMaxDynamicSharedMemorySize,
                             SMEM_BYTES);
        attr_set = true;
    }
    gru_scan_persistent<<<128, 256, SMEM_BYTES>>>(
        gates_p, gates_h, Wf, p_bhh, h_bhh, op, hbuf, HfW);

    // attention
    gemm_tf32<false><<<dim3(HDIM / 128, MB / 128), 256>>>(
        op, WyT, nullptr, WyM, MB, HDIM, HDIM);
    gemm_tiled<false, false><<<dim3(HDIM / 128, 1), 256>>>(
        hbuf, W_h, nullptr, Whs, BDIM, HDIM, HDIM);
    attn_kernel<<<128, 256>>>(WyM, Whs, W_alpha, op, rs);

    // h_star and classifier
    gemm_tiled<false, false><<<dim3(HDIM / 128, 1), 256>>>(
        rs, W_p, nullptr, G1, BDIM, HDIM, HDIM);
    gemm_tiled<false, false><<<dim3(HDIM / 128, 1), 256>>>(
        hbuf, W_x, nullptr, G2, BDIM, HDIM, HDIM);
    combine_tanh<<<(BH + 255) / 256, 256>>>(G1, G2, hstar, BH);
    final_kernel<<<128, 128>>>(hstar, out_w, out_b, (float*)d_out);
}